// round 5
// baseline (speedup 1.0000x reference)
#include <cuda_runtime.h>

#define N_EQ    131072
#define NTILES  8704            // 139264 / 16 points per tile
#define TILE_EQ 8192
#define TILE_IB 8448
#define NU      0.0031830988618379067154f

typedef unsigned long long u64;

__device__ __forceinline__ u64 pk2(float lo, float hi) {
    u64 r; asm("mov.b64 %0, {%1, %2};" : "=l"(r) : "f"(lo), "f"(hi)); return r;
}
__device__ __forceinline__ void upk2(u64 v, float& lo, float& hi) {
    asm("mov.b64 {%0, %1}, %2;" : "=f"(lo), "=f"(hi) : "l"(v));
}
__device__ __forceinline__ void fma2(u64& d, u64 a, u64 b) {
    asm("fma.rn.f32x2 %0, %1, %2, %0;" : "+l"(d) : "l"(a), "l"(b));
}
__device__ __forceinline__ u64 add2(u64 a, u64 b) {
    u64 r; asm("add.rn.f32x2 %0, %1, %2;" : "=l"(r) : "l"(a), "l"(b)); return r;
}
__device__ __forceinline__ float hadd2(u64 v) {
    float lo, hi; upk2(v, lo, hi); return lo + hi;
}
__device__ __forceinline__ float tanhf_fast(float z) {
    float e = __expf(2.0f * z);
    return __fdividef(e - 1.0f, e + 1.0f);
}

// Shared memory (bytes):
//   sWk : 3 layers x 64 kp x 128 j u64          = 196608 @ 0
//   st  : 16 pt x 262 u64 (256 used + 6 pad)    =  33536 @ 196608
//   sW4 : 64 u64                                 =    512 @ 230144
// total = 230656  (<= ~232448 limit)
#define ST_STRIDE 262
#define SMEM_BYTES 230656

extern __shared__ char smem_raw[];

__global__ __launch_bounds__(512, 1)
void pinn_kernel(const float* __restrict__ tx_eq,
                 const float* __restrict__ tx_init,
                 const float* __restrict__ tx_bnd,
                 const float* __restrict__ W0, const float* __restrict__ b0,
                 const float* __restrict__ W1, const float* __restrict__ b1,
                 const float* __restrict__ W2, const float* __restrict__ b2,
                 const float* __restrict__ W3, const float* __restrict__ b3,
                 const float* __restrict__ W4, const float* __restrict__ b4,
                 float* __restrict__ out)
{
    u64* sWk = (u64*)smem_raw;                    // [l][kp][j]
    u64* stU = (u64*)(smem_raw + 196608);         // [pt][ST_STRIDE]
    u64* sW4 = (u64*)(smem_raw + 230144);         // [kp]

    const int tid  = threadIdx.x;
    const int lane = tid & 31;
    const int w    = tid >> 5;        // 0..15
    const int Wj   = w & 3;           // j-group of warp
    const int Wc   = w >> 2;          // pt-group of warp
    const int jg   = lane >> 2;       // 0..7
    const int cg   = lane & 3;        // 0..3
    const int jb   = Wj * 32 + jg * 4;    // thread's 4 neurons jb..jb+3
    const int pt   = Wc * 4 + cg;          // thread's point 0..15

    // ---- Build k-pair-interleaved weights in smem (once; persistent) ----
    {
        const float* Wsrc[3] = { W1, W2, W3 };
        #pragma unroll
        for (int l = 0; l < 3; l++) {
            const float* Wm = Wsrc[l];
            for (int i = tid; i < 8192; i += 512) {
                const int kp = i >> 7, j = i & 127;
                sWk[l * 8192 + i] = pk2(Wm[(2*kp) * 128 + j], Wm[(2*kp+1) * 128 + j]);
            }
        }
        if (tid < 64) sW4[tid] = pk2(W4[2*tid], W4[2*tid+1]);
    }

    // Layer-0 params for this thread's fixed kp0 = tid & 63 (j = 2kp0, 2kp0+1)
    const int k0 = tid & 63;
    const float l0t0 = __ldg(W0 + 2*k0),       l0t1 = __ldg(W0 + 2*k0 + 1);
    const float l0x0 = __ldg(W0 + 128 + 2*k0), l0x1 = __ldg(W0 + 128 + 2*k0 + 1);
    const float l0b0 = __ldg(b0 + 2*k0),       l0b1 = __ldg(b0 + 2*k0 + 1);
    // Biases for layers 1..3, this thread's 4 neurons
    float bl[3][4];
    #pragma unroll
    for (int n = 0; n < 4; n++) {
        bl[0][n] = __ldg(b1 + jb + n);
        bl[1][n] = __ldg(b2 + jb + n);
        bl[2][n] = __ldg(b3 + jb + n);
    }
    const float b4s = __ldg(b4);
    __syncthreads();

    for (int tile = blockIdx.x; tile < NTILES; tile += gridDim.x) {
        const float2* src;
        if (tile < TILE_EQ)      src = (const float2*)tx_eq  + tile * 16;
        else if (tile < TILE_IB) src = (const float2*)tx_init + (tile - TILE_EQ) * 16;
        else                     src = (const float2*)tx_bnd  + (tile - TILE_IB) * 16;

        // ---- Layer 0: 2 -> 128, tanh; thread handles (pt0,k0) and (pt0+8,k0) ----
        {
            const int pt0 = tid >> 6;   // 0..7
            #pragma unroll
            for (int it = 0; it < 2; it++) {
                const int p = pt0 + 8 * it;
                const float2 t = __ldg(src + p);
                float a[2], at[2], ax[2], axx[2];
                #pragma unroll
                for (int m = 0; m < 2; m++) {
                    const float wt = m ? l0t1 : l0t0;
                    const float wx = m ? l0x1 : l0x0;
                    const float bb = m ? l0b1 : l0b0;
                    const float z  = fmaf(wt, t.x, fmaf(wx, t.y, bb));
                    const float av = tanhf_fast(z);
                    const float ap = 1.0f - av * av;
                    a[m] = av; at[m] = ap * wt; ax[m] = ap * wx;
                    axx[m] = -2.0f * av * ax[m] * wx;
                }
                u64* d = stU + p * ST_STRIDE + k0 * 4;
                ((ulonglong2*)d)[0] = make_ulonglong2(pk2(a[0], a[1]),  pk2(at[0],  at[1]));
                ((ulonglong2*)d)[1] = make_ulonglong2(pk2(ax[0], ax[1]), pk2(axx[0], axx[1]));
            }
        }
        __syncthreads();

        // ---- Layers 1..3: 128 -> 128, k-pair packed forward-mode AD ----
        #pragma unroll
        for (int l = 0; l < 3; l++) {
            const u64* Wb = sWk + l * 8192 + jb;
            const u64* sp = stU + pt * ST_STRIDE;

            u64 acc[4][4];   // [state][neuron]
            #pragma unroll
            for (int s = 0; s < 4; s++)
                #pragma unroll
                for (int n = 0; n < 4; n++) acc[s][n] = 0ull;

            #pragma unroll 8
            for (int kp = 0; kp < 64; kp++) {
                const ulonglong2 w01 = *(const ulonglong2*)(Wb + kp * 128);
                const ulonglong2 w23 = *(const ulonglong2*)(Wb + kp * 128 + 2);
                const ulonglong2 sa  = *(const ulonglong2*)(sp + kp * 4);      // (a,t)
                const ulonglong2 sb  = *(const ulonglong2*)(sp + kp * 4 + 2);  // (x,xx)

                fma2(acc[0][0], w01.x, sa.x); fma2(acc[0][1], w01.y, sa.x);
                fma2(acc[0][2], w23.x, sa.x); fma2(acc[0][3], w23.y, sa.x);
                fma2(acc[1][0], w01.x, sa.y); fma2(acc[1][1], w01.y, sa.y);
                fma2(acc[1][2], w23.x, sa.y); fma2(acc[1][3], w23.y, sa.y);
                fma2(acc[2][0], w01.x, sb.x); fma2(acc[2][1], w01.y, sb.x);
                fma2(acc[2][2], w23.x, sb.x); fma2(acc[2][3], w23.y, sb.x);
                fma2(acc[3][0], w01.x, sb.y); fma2(acc[3][1], w01.y, sb.y);
                fma2(acc[3][2], w23.x, sb.y); fma2(acc[3][3], w23.y, sb.y);
            }
            __syncthreads();   // all reads of this layer done before rewrites

            float a[4], at[4], ax[4], axx[4];
            #pragma unroll
            for (int n = 0; n < 4; n++) {
                const float z   = hadd2(acc[0][n]) + bl[l][n];
                const float zt  = hadd2(acc[1][n]);
                const float zx  = hadd2(acc[2][n]);
                const float zxx = hadd2(acc[3][n]);
                const float av  = tanhf_fast(z);
                const float ap  = 1.0f - av * av;
                a[n]  = av;
                at[n] = ap * zt;
                ax[n] = ap * zx;
                axx[n] = fmaf(-2.0f * av * ax[n], zx, ap * zxx);
            }
            {
                const int kp0 = jb >> 1;
                u64* d0 = stU + pt * ST_STRIDE + kp0 * 4;
                ((ulonglong2*)d0)[0] = make_ulonglong2(pk2(a[0], a[1]),  pk2(at[0],  at[1]));
                ((ulonglong2*)d0)[1] = make_ulonglong2(pk2(ax[0], ax[1]), pk2(axx[0], axx[1]));
                u64* d1 = d0 + 4;
                ((ulonglong2*)d1)[0] = make_ulonglong2(pk2(a[2], a[3]),  pk2(at[2],  at[3]));
                ((ulonglong2*)d1)[1] = make_ulonglong2(pk2(ax[2], ax[3]), pk2(axx[2], axx[3]));
            }
            __syncthreads();
        }

        // ---- Layer 4: 128 -> 1 linear; warp w reduces point pt=w ----
        {
            u64 r0 = 0ull, r1 = 0ull, r2 = 0ull, r3 = 0ull;
            const u64* sp = stU + w * ST_STRIDE;
            #pragma unroll
            for (int m = 0; m < 2; m++) {
                const int kp = lane + 32 * m;
                const u64 wv = sW4[kp];
                const ulonglong2 sa = *(const ulonglong2*)(sp + kp * 4);
                const ulonglong2 sb = *(const ulonglong2*)(sp + kp * 4 + 2);
                fma2(r0, wv, sa.x);
                fma2(r1, wv, sa.y);
                fma2(r2, wv, sb.x);
                fma2(r3, wv, sb.y);
            }
            #pragma unroll
            for (int off = 16; off > 0; off >>= 1) {
                r0 = add2(r0, __shfl_down_sync(0xffffffffu, r0, off));
                r1 = add2(r1, __shfl_down_sync(0xffffffffu, r1, off));
                r2 = add2(r2, __shfl_down_sync(0xffffffffu, r2, off));
                r3 = add2(r3, __shfl_down_sync(0xffffffffu, r3, off));
            }
            if (lane == 0) {
                const float u   = hadd2(r0) + b4s;
                const float ut  = hadd2(r1);
                const float ux  = hadd2(r2);
                const float uxx = hadd2(r3);
                out[tile * 16 + w] = (tile < TILE_EQ) ? (fmaf(u, ux, ut) - NU * uxx) : u;
            }
        }
        __syncthreads();   // layer-4 reads done before next tile's layer-0 stores
    }
}

extern "C" void kernel_launch(void* const* d_in, const int* in_sizes, int n_in,
                              void* d_out, int out_size)
{
    const float* tx_eq   = (const float*)d_in[0];
    const float* tx_init = (const float*)d_in[1];
    const float* tx_bnd  = (const float*)d_in[2];
    const float* W0 = (const float*)d_in[3];
    const float* b0 = (const float*)d_in[4];
    const float* W1 = (const float*)d_in[5];
    const float* b1 = (const float*)d_in[6];
    const float* W2 = (const float*)d_in[7];
    const float* b2 = (const float*)d_in[8];
    const float* W3 = (const float*)d_in[9];
    const float* b3 = (const float*)d_in[10];
    const float* W4 = (const float*)d_in[11];
    const float* b4 = (const float*)d_in[12];
    float* out = (float*)d_out;

    cudaFuncSetAttribute(pinn_kernel,
                         cudaFuncAttributeMaxDynamicSharedMemorySize,
                         SMEM_BYTES);

    int sms = 148;
    cudaDeviceGetAttribute(&sms, cudaDevAttrMultiProcessorCount, 0);
    if (sms > NTILES) sms = NTILES;

    pinn_kernel<<<sms, 512, SMEM_BYTES>>>(
        tx_eq, tx_init, tx_bnd,
        W0, b0, W1, b1, W2, b2, W3, b3, W4, b4,
        out);
}

// round 7
// speedup vs baseline: 1.8465x; 1.8465x over previous
#include <cuda_runtime.h>
#include <cuda_bf16.h>
#include <stdint.h>

#define NTILES 4352          // 139264 / 32 points
#define TEQ    4096
#define TIB    4224
#define NU     0.0031830988618379067154f

// W1..W3 as bf16 h/l splits in mma-fragment-linear layout:
// [l][ks][nt][lane] -> uint4{bh0, bh1, bl0, bl1}
__device__ uint4 g_wfrag[12288];

__device__ __forceinline__ uint32_t pkbf(float lo, float hi) {
    uint32_t r; asm("cvt.rn.bf16x2.f32 %0, %1, %2;" : "=r"(r) : "f"(hi), "f"(lo)); return r;
}
__device__ __forceinline__ void split2(float v0, float v1, uint32_t& h, uint32_t& l) {
    h = pkbf(v0, v1);
    float h0 = __uint_as_float(h << 16);
    float h1 = __uint_as_float(h & 0xffff0000u);
    l = pkbf(v0 - h0, v1 - h1);
}
__device__ __forceinline__ float tanhf_fast(float z) {
    float e = __expf(2.0f * z);
    return __fdividef(e - 1.0f, e + 1.0f);
}
__device__ __forceinline__ void mma16816(float* c, const uint32_t* a, uint32_t b0, uint32_t b1) {
    asm volatile(
        "mma.sync.aligned.m16n8k16.row.col.f32.bf16.bf16.f32 "
        "{%0,%1,%2,%3}, {%4,%5,%6,%7}, {%8,%9}, {%0,%1,%2,%3};"
        : "+f"(c[0]), "+f"(c[1]), "+f"(c[2]), "+f"(c[3])
        : "r"(a[0]), "r"(a[1]), "r"(a[2]), "r"(a[3]), "r"(b0), "r"(b1));
}

// ---- prep: split W1..3 to bf16 h/l fragment-linear scratch ----
__global__ void prep_kernel(const float* __restrict__ W1,
                            const float* __restrict__ W2,
                            const float* __restrict__ W3)
{
    const int gt   = blockIdx.x * blockDim.x + threadIdx.x;   // 0..12287
    const int lane = gt & 31;
    const int wi   = gt >> 5;                                 // 0..383
    const int nt   = wi & 15;
    const int ks   = (wi >> 4) & 7;
    const int l    = wi >> 7;
    const float* W = (l == 0) ? W1 : (l == 1) ? W2 : W3;
    const int j  = nt * 8 + (lane >> 2);
    const int k0 = ks * 16 + 2 * (lane & 3);
    const float w00 = W[(k0    ) * 128 + j];
    const float w01 = W[(k0 + 1) * 128 + j];
    const float w10 = W[(k0 + 8) * 128 + j];
    const float w11 = W[(k0 + 9) * 128 + j];
    uint32_t h0, l0, h1, l1;
    split2(w00, w01, h0, l0);
    split2(w10, w11, h1, l1);
    g_wfrag[wi * 32 + lane] = make_uint4(h0, h1, l0, l1);
}

// smem map (bytes): sWf 196608 | exA 16640 | exX 16640 | sB 1536 | sW4 512
#define SMEM_BYTES 231936

extern __shared__ char smem_raw[];

__global__ __launch_bounds__(256, 1)
void pinn_mma(const float* __restrict__ tx_eq, const float* __restrict__ tx_init,
              const float* __restrict__ tx_bnd,
              const float* __restrict__ W0, const float* __restrict__ b0,
              const float* __restrict__ b1, const float* __restrict__ b2,
              const float* __restrict__ b3,
              const float* __restrict__ W4, const float* __restrict__ b4,
              float* __restrict__ out)
{
    uint4* sWf = (uint4*)smem_raw;
    float* exA = (float*)(smem_raw + 196608);
    float* exX = (float*)(smem_raw + 213248);
    float* sB  = (float*)(smem_raw + 229888);
    float* sW4 = (float*)(smem_raw + 231424);

    const int tid  = threadIdx.x;
    const int lane = tid & 31;
    const int w    = tid >> 5;
    const int R    = w & 1;          // row-tile
    const int s    = w >> 1;         // state: 0=a 1=t 2=x 3=xx
    const int q    = lane & 3;
    const int ra   = 16 * R + (lane >> 2);
    const int rb   = ra + 8;

    for (int i = tid; i < 12288; i += 256) sWf[i] = g_wfrag[i];
    if (tid < 128) {
        sB[tid]       = __ldg(b1 + tid);
        sB[128 + tid] = __ldg(b2 + tid);
        sB[256 + tid] = __ldg(b3 + tid);
        sW4[tid]      = __ldg(W4 + tid);
    }
    const float b4v = __ldg(b4);
    __syncthreads();

    for (int tile = blockIdx.x; tile < NTILES; tile += gridDim.x) {
        const float2* src;
        if (tile < TEQ)      src = (const float2*)tx_eq  + tile * 32;
        else if (tile < TIB) src = (const float2*)tx_init + (tile - TEQ) * 32;
        else                 src = (const float2*)tx_bnd  + (tile - TIB) * 32;

        const float2 Pa = __ldg(src + ra);
        const float2 Pb = __ldg(src + rb);

        float c[16][4];

        // ---- layer 0: every warp computes its state's seeds (C layout) ----
        #pragma unroll
        for (int nt = 0; nt < 16; nt++) {
            #pragma unroll
            for (int m = 0; m < 2; m++) {
                const int col = 8 * nt + 2 * q + m;
                const float wt = __ldg(W0 + col);
                const float wx = __ldg(W0 + 128 + col);
                const float bb = __ldg(b0 + col);
                const float za = fmaf(wt, Pa.x, fmaf(wx, Pa.y, bb));
                const float zb = fmaf(wt, Pb.x, fmaf(wx, Pb.y, bb));
                const float a0 = tanhf_fast(za), a1 = tanhf_fast(zb);
                const float p0 = 1.0f - a0 * a0, p1 = 1.0f - a1 * a1;
                float va, vb;
                if (s == 0)      { va = a0;       vb = a1; }
                else if (s == 1) { va = p0 * wt;  vb = p1 * wt; }
                else if (s == 2) { va = p0 * wx;  vb = p1 * wx; }
                else             { va = -2.0f * a0 * p0 * wx * wx;
                                   vb = -2.0f * a1 * p1 * wx * wx; }
                c[nt][m] = va; c[nt][2 + m] = vb;
            }
        }

        // ---- 3 hidden GEMM layers ----
        #pragma unroll 1
        for (int l = 0; l < 3; l++) {
            // pack current activations (C layout) -> next A fragments
            uint32_t aH[8][4], aL[8][4];
            #pragma unroll
            for (int ks = 0; ks < 8; ks++) {
                split2(c[2*ks][0],   c[2*ks][1],   aH[ks][0], aL[ks][0]);
                split2(c[2*ks][2],   c[2*ks][3],   aH[ks][1], aL[ks][1]);
                split2(c[2*ks+1][0], c[2*ks+1][1], aH[ks][2], aL[ks][2]);
                split2(c[2*ks+1][2], c[2*ks+1][3], aH[ks][3], aL[ks][3]);
            }
            #pragma unroll
            for (int nt = 0; nt < 16; nt++) {
                c[nt][0] = 0.f; c[nt][1] = 0.f; c[nt][2] = 0.f; c[nt][3] = 0.f;
            }
            const uint4* bp = sWf + l * 4096 + lane;
            #pragma unroll
            for (int ks = 0; ks < 8; ks++) {
                #pragma unroll
                for (int nt = 0; nt < 16; nt++) {
                    const uint4 B = bp[(ks * 16 + nt) * 32];
                    mma16816(c[nt], aH[ks], B.x, B.y);   // hh
                    mma16816(c[nt], aL[ks], B.x, B.y);   // lh
                    mma16816(c[nt], aH[ks], B.z, B.w);   // hl
                }
            }

            // ---- epilogue: tanh AD coupling via smem exchange ----
            if (s == 0) {
                #pragma unroll
                for (int nt = 0; nt < 16; nt++) {
                    const int col = 8 * nt + 2 * q;
                    const float bv0 = sB[l * 128 + col];
                    const float bv1 = sB[l * 128 + col + 1];
                    c[nt][0] = tanhf_fast(c[nt][0] + bv0);
                    c[nt][1] = tanhf_fast(c[nt][1] + bv1);
                    c[nt][2] = tanhf_fast(c[nt][2] + bv0);
                    c[nt][3] = tanhf_fast(c[nt][3] + bv1);
                    *(float2*)(exA + ra * 130 + col) = make_float2(c[nt][0], c[nt][1]);
                    *(float2*)(exA + rb * 130 + col) = make_float2(c[nt][2], c[nt][3]);
                }
            } else if (s == 2) {
                #pragma unroll
                for (int nt = 0; nt < 16; nt++) {
                    const int col = 8 * nt + 2 * q;
                    *(float2*)(exX + ra * 130 + col) = make_float2(c[nt][0], c[nt][1]);
                    *(float2*)(exX + rb * 130 + col) = make_float2(c[nt][2], c[nt][3]);
                }
            }
            __syncthreads();
            if (s != 0) {
                #pragma unroll
                for (int nt = 0; nt < 16; nt++) {
                    const int col = 8 * nt + 2 * q;
                    const float2 aA = *(const float2*)(exA + ra * 130 + col);
                    const float2 aB = *(const float2*)(exA + rb * 130 + col);
                    const float p0 = 1.0f - aA.x * aA.x, p1 = 1.0f - aA.y * aA.y;
                    const float p2 = 1.0f - aB.x * aB.x, p3 = 1.0f - aB.y * aB.y;
                    if (s == 3) {
                        const float2 xA = *(const float2*)(exX + ra * 130 + col);
                        const float2 xB = *(const float2*)(exX + rb * 130 + col);
                        c[nt][0] = p0 * fmaf(-2.0f * aA.x * xA.x, xA.x, c[nt][0]);
                        c[nt][1] = p1 * fmaf(-2.0f * aA.y * xA.y, xA.y, c[nt][1]);
                        c[nt][2] = p2 * fmaf(-2.0f * aB.x * xB.x, xB.x, c[nt][2]);
                        c[nt][3] = p3 * fmaf(-2.0f * aB.y * xB.y, xB.y, c[nt][3]);
                    } else {
                        c[nt][0] *= p0; c[nt][1] *= p1; c[nt][2] *= p2; c[nt][3] *= p3;
                    }
                }
            }
            __syncthreads();
        }

        // ---- layer 4: per-state dot with W4, quad reduce, combine ----
        {
            float d0 = 0.f, d1 = 0.f;
            #pragma unroll
            for (int nt = 0; nt < 16; nt++) {
                const int col = 8 * nt + 2 * q;
                const float w0v = sW4[col], w1v = sW4[col + 1];
                d0 = fmaf(w0v, c[nt][0], fmaf(w1v, c[nt][1], d0));
                d1 = fmaf(w0v, c[nt][2], fmaf(w1v, c[nt][3], d1));
            }
            d0 += __shfl_xor_sync(0xffffffffu, d0, 1);
            d0 += __shfl_xor_sync(0xffffffffu, d0, 2);
            d1 += __shfl_xor_sync(0xffffffffu, d1, 1);
            d1 += __shfl_xor_sync(0xffffffffu, d1, 2);
            if (q == 0) {
                exA[s * 32 + ra] = d0;
                exA[s * 32 + rb] = d1;
            }
            __syncthreads();
            if (w == 0) {
                const int row = lane;
                const float u   = exA[row] + b4v;
                const float ut  = exA[32 + row];
                const float ux  = exA[64 + row];
                const float uxx = exA[96 + row];
                out[tile * 32 + row] =
                    (tile < TEQ) ? (fmaf(u, ux, ut) - NU * uxx) : u;
            }
            __syncthreads();
        }
    }
}

extern "C" void kernel_launch(void* const* d_in, const int* in_sizes, int n_in,
                              void* d_out, int out_size)
{
    const float* tx_eq   = (const float*)d_in[0];
    const float* tx_init = (const float*)d_in[1];
    const float* tx_bnd  = (const float*)d_in[2];
    const float* W0 = (const float*)d_in[3];
    const float* b0 = (const float*)d_in[4];
    const float* W1 = (const float*)d_in[5];
    const float* b1 = (const float*)d_in[6];
    const float* W2 = (const float*)d_in[7];
    const float* b2 = (const float*)d_in[8];
    const float* W3 = (const float*)d_in[9];
    const float* b3 = (const float*)d_in[10];
    const float* W4 = (const float*)d_in[11];
    const float* b4 = (const float*)d_in[12];
    float* out = (float*)d_out;

    prep_kernel<<<48, 256>>>(W1, W2, W3);

    cudaFuncSetAttribute(pinn_mma, cudaFuncAttributeMaxDynamicSharedMemorySize, SMEM_BYTES);
    int sms = 148;
    cudaDeviceGetAttribute(&sms, cudaDevAttrMultiProcessorCount, 0);
    if (sms > NTILES) sms = NTILES;

    pinn_mma<<<sms, 256, SMEM_BYTES>>>(tx_eq, tx_init, tx_bnd,
        W0, b0, b1, b2, b3, W4, b4, out);
}

// round 9
// speedup vs baseline: 1.8721x; 1.0139x over previous
#include <cuda_runtime.h>
#include <cuda_bf16.h>
#include <stdint.h>

#define NTILES 4352          // 139264 / 32 points
#define TEQ    4096
#define TIB    4224
#define NU     0.0031830988618379067154f

// W1..W3 bf16 fragments, h and l splits separate: [l][ks][nt][lane] -> uint2{b0,b1}
__device__ uint2 g_wfH[12288];
__device__ uint2 g_wfL[12288];

__device__ __forceinline__ uint32_t pkbf(float lo, float hi) {
    uint32_t r; asm("cvt.rn.bf16x2.f32 %0, %1, %2;" : "=r"(r) : "f"(hi), "f"(lo)); return r;
}
__device__ __forceinline__ void split2(float v0, float v1, uint32_t& h, uint32_t& l) {
    h = pkbf(v0, v1);
    float h0 = __uint_as_float(h << 16);
    float h1 = __uint_as_float(h & 0xffff0000u);
    l = pkbf(v0 - h0, v1 - h1);
}
__device__ __forceinline__ float tanhf_fast(float z) {
    float e = __expf(2.0f * z);
    return __fdividef(e - 1.0f, e + 1.0f);
}
__device__ __forceinline__ void mma16816(float* c, const uint32_t* a, uint32_t b0, uint32_t b1) {
    asm volatile(
        "mma.sync.aligned.m16n8k16.row.col.f32.bf16.bf16.f32 "
        "{%0,%1,%2,%3}, {%4,%5,%6,%7}, {%8,%9}, {%0,%1,%2,%3};"
        : "+f"(c[0]), "+f"(c[1]), "+f"(c[2]), "+f"(c[3])
        : "r"(a[0]), "r"(a[1]), "r"(a[2]), "r"(a[3]), "r"(b0), "r"(b1));
}

__global__ void prep_kernel(const float* __restrict__ W1,
                            const float* __restrict__ W2,
                            const float* __restrict__ W3)
{
    const int gt   = blockIdx.x * blockDim.x + threadIdx.x;   // 0..12287
    const int lane = gt & 31;
    const int wi   = gt >> 5;
    const int nt   = wi & 15;
    const int ks   = (wi >> 4) & 7;
    const int l    = wi >> 7;
    const float* W = (l == 0) ? W1 : (l == 1) ? W2 : W3;
    const int j  = nt * 8 + (lane >> 2);
    const int k0 = ks * 16 + 2 * (lane & 3);
    uint32_t h0, l0, h1, l1;
    split2(W[(k0    ) * 128 + j], W[(k0 + 1) * 128 + j], h0, l0);
    split2(W[(k0 + 8) * 128 + j], W[(k0 + 9) * 128 + j], h1, l1);
    g_wfH[wi * 32 + lane] = make_uint2(h0, h1);
    g_wfL[wi * 32 + lane] = make_uint2(l0, l1);
}

// smem: sWfH 98304 | sWfL 98304 | exA 16640 (stride 130) | exX 16640
#define EXA_OFF  196608
#define EXX_OFF  213248
#define SMEM_BYTES 229888

extern __shared__ char smem_raw[];

__global__ __launch_bounds__(256, 1)
void pinn_mma(const float* __restrict__ tx_eq, const float* __restrict__ tx_init,
              const float* __restrict__ tx_bnd,
              const float* __restrict__ W0, const float* __restrict__ b0,
              const float* __restrict__ b1, const float* __restrict__ b2,
              const float* __restrict__ b3,
              const float* __restrict__ W4, const float* __restrict__ b4,
              float* __restrict__ out)
{
    uint2* sWfH = (uint2*)smem_raw;
    uint2* sWfL = (uint2*)(smem_raw + 98304);
    float* exA  = (float*)(smem_raw + EXA_OFF);
    float* exX  = (float*)(smem_raw + EXX_OFF);

    const int tid  = threadIdx.x;
    const int lane = tid & 31;
    const int w    = tid >> 5;
    const int R    = w & 1;          // row-tile
    const int s    = w >> 1;         // state: 0=a 1=t 2=x 3=xx
    const int q    = lane & 3;
    const int ra   = 16 * R + (lane >> 2);
    const int rb   = ra + 8;

    {
        uint2* d = (uint2*)smem_raw;
        for (int i = tid; i < 12288; i += 256) { d[i] = g_wfH[i]; d[12288 + i] = g_wfL[i]; }
    }
    const float b4v = __ldg(b4);
    __syncthreads();

    for (int tile = blockIdx.x; tile < NTILES; tile += gridDim.x) {
        const float2* src;
        if (tile < TEQ)      src = (const float2*)tx_eq  + tile * 32;
        else if (tile < TIB) src = (const float2*)tx_init + (tile - TEQ) * 32;
        else                 src = (const float2*)tx_bnd  + (tile - TIB) * 32;

        const float2 Pa = __ldg(src + ra);
        const float2 Pb = __ldg(src + rb);

        float c[16][4];

        // ---- layer 0: every warp computes its state's seeds (C layout) ----
        #pragma unroll
        for (int nt = 0; nt < 16; nt++) {
            #pragma unroll
            for (int m = 0; m < 2; m++) {
                const int col = 8 * nt + 2 * q + m;
                const float wt = __ldg(W0 + col);
                const float wx = __ldg(W0 + 128 + col);
                const float bb = __ldg(b0 + col);
                const float za = fmaf(wt, Pa.x, fmaf(wx, Pa.y, bb));
                const float zb = fmaf(wt, Pb.x, fmaf(wx, Pb.y, bb));
                const float a0 = tanhf_fast(za), a1 = tanhf_fast(zb);
                const float p0 = 1.0f - a0 * a0, p1 = 1.0f - a1 * a1;
                float va, vb;
                if (s == 0)      { va = a0;       vb = a1; }
                else if (s == 1) { va = p0 * wt;  vb = p1 * wt; }
                else if (s == 2) { va = p0 * wx;  vb = p1 * wx; }
                else             { va = -2.0f * a0 * p0 * wx * wx;
                                   vb = -2.0f * a1 * p1 * wx * wx; }
                c[nt][m] = va; c[nt][2 + m] = vb;
            }
        }

        // ---- 3 hidden GEMM layers ----
        #pragma unroll 1
        for (int l = 0; l < 3; l++) {
            uint32_t aH[8][4], aL[8][4];
            #pragma unroll
            for (int ks = 0; ks < 8; ks++) {
                split2(c[2*ks][0],   c[2*ks][1],   aH[ks][0], aL[ks][0]);
                split2(c[2*ks][2],   c[2*ks][3],   aH[ks][1], aL[ks][1]);
                split2(c[2*ks+1][0], c[2*ks+1][1], aH[ks][2], aL[ks][2]);
                split2(c[2*ks+1][2], c[2*ks+1][3], aH[ks][3], aL[ks][3]);
            }
            #pragma unroll
            for (int nt = 0; nt < 16; nt++) {
                c[nt][0] = 0.f; c[nt][1] = 0.f; c[nt][2] = 0.f; c[nt][3] = 0.f;
            }
            const uint2* bh = sWfH + l * 4096 + lane;
            const uint2* bl = sWfL + l * 4096 + lane;
            #pragma unroll
            for (int ks = 0; ks < 8; ks++) {
                const int base = ks * 16;
                // pass 1: hh over all nt (16 independent accumulator chains)
                #pragma unroll
                for (int nt = 0; nt < 16; nt++) {
                    const uint2 B = bh[(base + nt) * 32];
                    mma16816(c[nt], aH[ks], B.x, B.y);
                }
                // pass 2: lh
                #pragma unroll
                for (int nt = 0; nt < 16; nt++) {
                    const uint2 B = bh[(base + nt) * 32];
                    mma16816(c[nt], aL[ks], B.x, B.y);
                }
                // pass 3: hl
                #pragma unroll
                for (int nt = 0; nt < 16; nt++) {
                    const uint2 B = bl[(base + nt) * 32];
                    mma16816(c[nt], aH[ks], B.x, B.y);
                }
            }

            // ---- epilogue: tanh AD coupling via smem exchange ----
            const float* bb = (l == 0) ? b1 : (l == 1) ? b2 : b3;
            if (s == 0) {
                #pragma unroll
                for (int nt = 0; nt < 16; nt++) {
                    const int col = 8 * nt + 2 * q;
                    const float bv0 = __ldg(bb + col);
                    const float bv1 = __ldg(bb + col + 1);
                    c[nt][0] = tanhf_fast(c[nt][0] + bv0);
                    c[nt][1] = tanhf_fast(c[nt][1] + bv1);
                    c[nt][2] = tanhf_fast(c[nt][2] + bv0);
                    c[nt][3] = tanhf_fast(c[nt][3] + bv1);
                    *(float2*)(exA + ra * 130 + col) = make_float2(c[nt][0], c[nt][1]);
                    *(float2*)(exA + rb * 130 + col) = make_float2(c[nt][2], c[nt][3]);
                }
            } else if (s == 2) {
                #pragma unroll
                for (int nt = 0; nt < 16; nt++) {
                    const int col = 8 * nt + 2 * q;
                    *(float2*)(exX + ra * 130 + col) = make_float2(c[nt][0], c[nt][1]);
                    *(float2*)(exX + rb * 130 + col) = make_float2(c[nt][2], c[nt][3]);
                }
            }
            __syncthreads();
            if (s != 0) {
                #pragma unroll
                for (int nt = 0; nt < 16; nt++) {
                    const int col = 8 * nt + 2 * q;
                    const float2 aA = *(const float2*)(exA + ra * 130 + col);
                    const float2 aB = *(const float2*)(exA + rb * 130 + col);
                    const float p0 = 1.0f - aA.x * aA.x, p1 = 1.0f - aA.y * aA.y;
                    const float p2 = 1.0f - aB.x * aB.x, p3 = 1.0f - aB.y * aB.y;
                    if (s == 3) {
                        const float2 xA = *(const float2*)(exX + ra * 130 + col);
                        const float2 xB = *(const float2*)(exX + rb * 130 + col);
                        c[nt][0] = p0 * fmaf(-2.0f * aA.x * xA.x, xA.x, c[nt][0]);
                        c[nt][1] = p1 * fmaf(-2.0f * aA.y * xA.y, xA.y, c[nt][1]);
                        c[nt][2] = p2 * fmaf(-2.0f * aB.x * xB.x, xB.x, c[nt][2]);
                        c[nt][3] = p3 * fmaf(-2.0f * aB.y * xB.y, xB.y, c[nt][3]);
                    } else {
                        c[nt][0] *= p0; c[nt][1] *= p1; c[nt][2] *= p2; c[nt][3] *= p3;
                    }
                }
            }
            __syncthreads();
        }

        // ---- layer 4: per-state dot with W4, quad reduce, combine ----
        {
            float d0 = 0.f, d1 = 0.f;
            #pragma unroll
            for (int nt = 0; nt < 16; nt++) {
                const int col = 8 * nt + 2 * q;
                const float w0v = __ldg(W4 + col), w1v = __ldg(W4 + col + 1);
                d0 = fmaf(w0v, c[nt][0], fmaf(w1v, c[nt][1], d0));
                d1 = fmaf(w0v, c[nt][2], fmaf(w1v, c[nt][3], d1));
            }
            d0 += __shfl_xor_sync(0xffffffffu, d0, 1);
            d0 += __shfl_xor_sync(0xffffffffu, d0, 2);
            d1 += __shfl_xor_sync(0xffffffffu, d1, 1);
            d1 += __shfl_xor_sync(0xffffffffu, d1, 2);
            if (q == 0) {
                exA[s * 32 + ra] = d0;
                exA[s * 32 + rb] = d1;
            }
            __syncthreads();
            if (w == 0) {
                const int row = lane;
                const float u   = exA[row] + b4v;
                const float ut  = exA[32 + row];
                const float ux  = exA[64 + row];
                const float uxx = exA[96 + row];
                out[tile * 32 + row] =
                    (tile < TEQ) ? (fmaf(u, ux, ut) - NU * uxx) : u;
            }
            __syncthreads();
        }
    }
}

extern "C" void kernel_launch(void* const* d_in, const int* in_sizes, int n_in,
                              void* d_out, int out_size)
{
    const float* tx_eq   = (const float*)d_in[0];
    const float* tx_init = (const float*)d_in[1];
    const float* tx_bnd  = (const float*)d_in[2];
    const float* W0 = (const float*)d_in[3];
    const float* b0 = (const float*)d_in[4];
    const float* W1 = (const float*)d_in[5];
    const float* b1 = (const float*)d_in[6];
    const float* W2 = (const float*)d_in[7];
    const float* b2 = (const float*)d_in[8];
    const float* W3 = (const float*)d_in[9];
    const float* b3 = (const float*)d_in[10];
    const float* W4 = (const float*)d_in[11];
    const float* b4 = (const float*)d_in[12];
    float* out = (float*)d_out;

    prep_kernel<<<48, 256>>>(W1, W2, W3);

    cudaFuncSetAttribute(pinn_mma, cudaFuncAttributeMaxDynamicSharedMemorySize, SMEM_BYTES);
    int sms = 148;
    cudaDeviceGetAttribute(&sms, cudaDevAttrMultiProcessorCount, 0);
    if (sms > NTILES) sms = NTILES;

    pinn_mma<<<sms, 256, SMEM_BYTES>>>(tx_eq, tx_init, tx_bnd,
        W0, b0, b1, b2, b3, W4, b4, out);
}